// round 8
// baseline (speedup 1.0000x reference)
#include <cuda_runtime.h>
#include <math.h>

#define BATCH 8192
#define DIM   2048
#define WORDS 64          // 2048 bits / 32 per row
#define NBLK  128         // forward grid
#define FTH   64          // forward block threads (1 row per thread)

// ---------------- device scratch (no allocations allowed) ----------------
__device__ float4             g_tab1[256 * 3];  // 8-step products of K matrices
__device__ float4             g_tab2[256 * 3];  // 7 K's + trailing diag(e), last byte
__device__ float              g_pi[4];
__device__ unsigned           g_packed[BATCH * WORDS];
__device__ unsigned long long g_acc;            // fixed-point (2^32) sum of logp
__device__ unsigned           g_done;           // block completion counter

// =================== K1: pack + precompute + reset =======================
__global__ void __launch_bounds__(256) prep_kernel(const int* __restrict__ y,
                                                   const float* __restrict__ T,
                                                   const float* __restrict__ E,
                                                   const float* __restrict__ S) {
    if (blockIdx.x < 2048) {
        // ---- ballot-pack: warp packs 1024 consecutive ints -> 32 words ----
        int warp_id = (blockIdx.x * 256 + threadIdx.x) >> 5;   // 0..16383
        int lane    = threadIdx.x & 31;
        const int* p = y + (size_t)warp_id * 1024;
        unsigned my = 0;
        #pragma unroll
        for (int r = 0; r < 32; r++) {
            int v = __ldcs(p + r * 32 + lane);                 // streaming, read-once
            unsigned b = __ballot_sync(0xFFFFFFFFu, v != 0);
            if (lane == r) my = b;
        }
        g_packed[warp_id * 32 + lane] = my;                    // coalesced 128B store
        return;
    }

    // ---- precompute block (blockIdx.x == 2048): tables in fp64 ----
    int tid = threadIdx.x;
    if (tid == 0) { g_acc = 0ull; g_done = 0u; }

    double W[3][3], e[2][3];
    for (int i = 0; i < 3; i++) {
        double t0 = T[i * 3 + 0], t1 = T[i * 3 + 1], t2 = T[i * 3 + 2];
        double m = fmax(t0, fmax(t1, t2));
        double s0 = exp(t0 - m), s1 = exp(t1 - m), s2 = exp(t2 - m);
        double Z = s0 + s1 + s2;
        W[i][0] = s0 / Z; W[i][1] = s1 / Z; W[i][2] = s2 / Z;
        double a = E[i * 2 + 0], b = E[i * 2 + 1];
        double mm = fmax(a, b);
        double ea = exp(a - mm), eb = exp(b - mm);
        double Ze = ea + eb;
        e[0][i] = ea / Ze;      // P(obs=0 | state i)
        e[1][i] = eb / Ze;      // P(obs=1 | state i)
    }

    #pragma unroll
    for (int second = 0; second < 2; second++) {
        int byte = tid;        // 0..255
        double P[3][3];
        {
            int b0 = byte & 1;
            for (int i = 0; i < 3; i++)
                for (int j = 0; j < 3; j++)
                    P[i][j] = e[b0][i] * W[i][j];
        }
        int nk = second ? 7 : 8;
        for (int t = 1; t < nk; t++) {
            int bt = (byte >> t) & 1;
            double Q[3][3];
            for (int i = 0; i < 3; i++)
                for (int j = 0; j < 3; j++)
                    Q[i][j] = P[i][0] * (e[bt][0] * W[0][j])
                            + P[i][1] * (e[bt][1] * W[1][j])
                            + P[i][2] * (e[bt][2] * W[2][j]);
            for (int i = 0; i < 3; i++)
                for (int j = 0; j < 3; j++) P[i][j] = Q[i][j];
        }
        if (second) {          // trailing emission diag for the last timestep
            int b7 = (byte >> 7) & 1;
            for (int i = 0; i < 3; i++)
                for (int j = 0; j < 3; j++) P[i][j] *= e[b7][j];
        }
        float4* dst = (second ? g_tab2 : g_tab1) + byte * 3;
        for (int i = 0; i < 3; i++)
            dst[i] = make_float4((float)P[i][0], (float)P[i][1], (float)P[i][2], 0.f);
    }

    if (tid == 0) {
        double s0 = S[0], s1 = S[1], s2 = S[2];
        double m = fmax(s0, fmax(s1, s2));
        double a = exp(s0 - m), b = exp(s1 - m), d = exp(s2 - m);
        double Z = a + b + d;
        g_pi[0] = (float)(a / Z);
        g_pi[1] = (float)(b / Z);
        g_pi[2] = (float)(d / Z);
        g_pi[3] = 0.f;
    }
}

// =================== K2: forward chain + fused finalize ==================
__device__ __forceinline__ void mulmat(float& v0, float& v1, float& v2,
                                       float4 r0, float4 r1, float4 r2) {
    float n0 = fmaf(v0, r0.x, fmaf(v1, r1.x, v2 * r2.x));
    float n1 = fmaf(v0, r0.y, fmaf(v1, r1.y, v2 * r2.y));
    float n2 = fmaf(v0, r0.z, fmaf(v1, r1.z, v2 * r2.z));
    v0 = n0; v1 = n1; v2 = n2;
}

// apply pending power-of-2 scale (exact), then measure a new one from current v.
// Measurement runs off the critical chain; only the 3 multiplies are on it.
#define APPLY_MEASURE()                                             \
    do {                                                            \
        v0 *= scp; v1 *= scp; v2 *= scp; etot += ep;                \
        float s_ = v0 + v1 + v2;                                    \
        unsigned eb_ = __float_as_uint(s_) >> 23;                   \
        ep  = (int)eb_ - 127;                                       \
        scp = __uint_as_float((254u - eb_) << 23);                  \
    } while (0)

__global__ void __launch_bounds__(FTH) forward_kernel(float* __restrict__ out) {
    __shared__ float4   t1[768];            // 12 KB: 256 matrices of 3 float4 rows
    __shared__ unsigned sw[FTH][WORDS + 1]; // 16.6 KB: staged packed words (+pad)
    __shared__ double   red[FTH];
    int tid = threadIdx.x;

    #pragma unroll
    for (int i = tid; i < 768; i += FTH) t1[i] = g_tab1[i];
    // coalesced staging of this block's 64 rows x 64 words
    const unsigned* src = g_packed + (size_t)blockIdx.x * FTH * WORDS;
    #pragma unroll
    for (int i = tid; i < FTH * WORDS; i += FTH) sw[i >> 6][i & 63] = src[i];
    __syncthreads();

    float v0 = g_pi[0], v1 = g_pi[1], v2 = g_pi[2];
    int etot = 0, ep = 0;
    float scp = 1.0f;

    const unsigned* myw = sw[tid];
    unsigned word = myw[0];
    #pragma unroll 2
    for (int w = 0; w < WORDS - 1; w++) {
        unsigned nw = myw[w + 1];           // prefetch next word (LDS lat hidden)
        unsigned b0 = word & 255u, b1 = (word >> 8) & 255u;
        unsigned b2 = (word >> 16) & 255u, b3 = word >> 24;
        mulmat(v0, v1, v2, t1[b0 * 3], t1[b0 * 3 + 1], t1[b0 * 3 + 2]);
        mulmat(v0, v1, v2, t1[b1 * 3], t1[b1 * 3 + 1], t1[b1 * 3 + 2]);
        APPLY_MEASURE();
        mulmat(v0, v1, v2, t1[b2 * 3], t1[b2 * 3 + 1], t1[b2 * 3 + 2]);
        mulmat(v0, v1, v2, t1[b3 * 3], t1[b3 * 3 + 1], t1[b3 * 3 + 2]);
        APPLY_MEASURE();
        word = nw;
    }
    // last word: final byte uses table2 (7 K's + trailing emission diag)
    {
        unsigned b0 = word & 255u, b1 = (word >> 8) & 255u;
        unsigned b2 = (word >> 16) & 255u, b3 = word >> 24;
        mulmat(v0, v1, v2, t1[b0 * 3], t1[b0 * 3 + 1], t1[b0 * 3 + 2]);
        mulmat(v0, v1, v2, t1[b1 * 3], t1[b1 * 3 + 1], t1[b1 * 3 + 2]);
        APPLY_MEASURE();
        mulmat(v0, v1, v2, t1[b2 * 3], t1[b2 * 3 + 1], t1[b2 * 3 + 2]);
        const float4* m2 = g_tab2 + b3 * 3;          // L2-served, once per row
        mulmat(v0, v1, v2, __ldg(m2), __ldg(m2 + 1), __ldg(m2 + 2));
        // pending (scp, ep) is an exact identity — safe to drop here
    }
    float logp = logf(v0 + v1 + v2) + (float)etot * 0.69314718055994530942f;

    // ---- fused finalize: block reduce, fixed-point atomic, last block writes
    red[tid] = (double)logp;
    __syncthreads();
    #pragma unroll
    for (int off = FTH / 2; off > 0; off >>= 1) {
        if (tid < off) red[tid] += red[tid + off];
        __syncthreads();
    }
    if (tid == 0) {
        long long fx = __double2ll_rn(red[0] * 4294967296.0);   // 2^32 fixed point
        atomicAdd(&g_acc, (unsigned long long)fx);              // exact, associative
        __threadfence();
        unsigned prev = atomicAdd(&g_done, 1u);
        if (prev == NBLK - 1) {
            unsigned long long a = atomicAdd(&g_acc, 0ull);     // ordered read
            double tot = (double)(long long)a * (1.0 / 4294967296.0);
            out[0] = (float)(tot / (double)BATCH);
        }
    }
}

// ---------------- launch: 2 graph nodes ----------------
extern "C" void kernel_launch(void* const* d_in, const int* in_sizes, int n_in,
                              void* d_out, int out_size) {
    const int*   y = (const int*)d_in[0];
    const float* T = (const float*)d_in[1];
    const float* E = (const float*)d_in[2];
    const float* S = (const float*)d_in[3];

    prep_kernel<<<2049, 256>>>(y, T, E, S);      // 2048 pack blocks + 1 precompute
    forward_kernel<<<NBLK, FTH>>>((float*)d_out);
}

// round 11
// speedup vs baseline: 3.3714x; 3.3714x over previous
#include <cuda_runtime.h>
#include <math.h>

#define BATCH 8192
#define DIM   2048
#define WORDS 64           // 2048 bits / 32 per row
#define FBLK  128          // forward block threads
#define FROWS 32           // rows per forward block
#define FGRID (BATCH / FROWS)   // 256 forward blocks

// ---------------- device scratch (no allocations allowed) ----------------
__device__ float4             g_tab1[256 * 3];  // 8-step products of K matrices
__device__ float4             g_tab2[256 * 3];  // 7 K's + trailing diag(e), last byte
__device__ float              g_pi[4];
__device__ unsigned           g_packed[BATCH * WORDS];
__device__ unsigned long long g_acc;            // fixed-point (2^32) sum of logp
__device__ unsigned           g_done;           // block completion counter

// =================== K1: pack + fp32 precompute + reset ==================
__global__ void __launch_bounds__(256) prep_kernel(const int* __restrict__ y,
                                                   const float* __restrict__ T,
                                                   const float* __restrict__ E,
                                                   const float* __restrict__ S) {
    if (blockIdx.x < 2048) {
        // ---- ballot-pack: warp packs 1024 consecutive ints -> 32 words ----
        int warp_id = (blockIdx.x * 256 + threadIdx.x) >> 5;   // 0..16383
        int lane    = threadIdx.x & 31;
        const int* p = y + (size_t)warp_id * 1024;
        unsigned my = 0;
        #pragma unroll
        for (int r = 0; r < 32; r++) {
            int v = __ldcs(p + r * 32 + lane);                 // streaming, read-once
            unsigned b = __ballot_sync(0xFFFFFFFFu, v != 0);
            if (lane == r) my = b;
        }
        g_packed[warp_id * 32 + lane] = my;                    // coalesced 128B store
        return;
    }

    // ---- precompute block (blockIdx.x == 2048): tables in FP32 ----
    int tid = threadIdx.x;
    if (tid == 0) { g_acc = 0ull; g_done = 0u; }

    float W[3][3], e[2][3];
    #pragma unroll
    for (int i = 0; i < 3; i++) {
        float t0 = T[i * 3 + 0], t1 = T[i * 3 + 1], t2 = T[i * 3 + 2];
        float m = fmaxf(t0, fmaxf(t1, t2));
        float s0 = expf(t0 - m), s1 = expf(t1 - m), s2 = expf(t2 - m);
        float Z = s0 + s1 + s2;
        W[i][0] = s0 / Z; W[i][1] = s1 / Z; W[i][2] = s2 / Z;
        float a = E[i * 2 + 0], b = E[i * 2 + 1];
        float mm = fmaxf(a, b);
        float ea = expf(a - mm), eb = expf(b - mm);
        float Ze = ea + eb;
        e[0][i] = ea / Ze;      // P(obs=0 | state i)
        e[1][i] = eb / Ze;      // P(obs=1 | state i)
    }

    #pragma unroll
    for (int second = 0; second < 2; second++) {
        int byte = tid;         // 0..255
        float P[3][3];
        {
            int b0 = byte & 1;
            #pragma unroll
            for (int i = 0; i < 3; i++)
                #pragma unroll
                for (int j = 0; j < 3; j++)
                    P[i][j] = e[b0][i] * W[i][j];
        }
        int nk = second ? 7 : 8;
        for (int t = 1; t < nk; t++) {
            int bt = (byte >> t) & 1;
            float Q[3][3];
            #pragma unroll
            for (int i = 0; i < 3; i++)
                #pragma unroll
                for (int j = 0; j < 3; j++)
                    Q[i][j] = P[i][0] * (e[bt][0] * W[0][j])
                            + P[i][1] * (e[bt][1] * W[1][j])
                            + P[i][2] * (e[bt][2] * W[2][j]);
            #pragma unroll
            for (int i = 0; i < 3; i++)
                #pragma unroll
                for (int j = 0; j < 3; j++) P[i][j] = Q[i][j];
        }
        if (second) {           // trailing emission diag for the last timestep
            int b7 = (byte >> 7) & 1;
            #pragma unroll
            for (int i = 0; i < 3; i++)
                #pragma unroll
                for (int j = 0; j < 3; j++) P[i][j] *= e[b7][j];
        }
        float4* dst = (second ? g_tab2 : g_tab1) + byte * 3;
        #pragma unroll
        for (int i = 0; i < 3; i++)
            dst[i] = make_float4(P[i][0], P[i][1], P[i][2], 0.f);
    }

    if (tid == 0) {
        float s0 = S[0], s1 = S[1], s2 = S[2];
        float m = fmaxf(s0, fmaxf(s1, s2));
        float a = expf(s0 - m), b = expf(s1 - m), d = expf(s2 - m);
        float Z = a + b + d;
        g_pi[0] = a / Z; g_pi[1] = b / Z; g_pi[2] = d / Z; g_pi[3] = 0.f;
    }
}

// =================== K2: split forward chain + fused finalize =============
__device__ __forceinline__ void mulvec(float& v0, float& v1, float& v2,
                                       float4 r0, float4 r1, float4 r2) {
    float n0 = fmaf(v0, r0.x, fmaf(v1, r1.x, v2 * r2.x));
    float n1 = fmaf(v0, r0.y, fmaf(v1, r1.y, v2 * r2.y));
    float n2 = fmaf(v0, r0.z, fmaf(v1, r1.z, v2 * r2.z));
    v0 = n0; v1 = n1; v2 = n2;
}

// apply pending power-of-2 scale (exact), then measure a new one off-chain
#define VAM()                                                       \
    do {                                                            \
        v0 *= scp; v1 *= scp; v2 *= scp; etot += ep;                \
        float s_ = v0 + v1 + v2;                                    \
        unsigned eb_ = __float_as_uint(s_) >> 23;                   \
        ep  = (int)eb_ - 127;                                       \
        scp = __uint_as_float((254u - eb_) << 23);                  \
    } while (0)

#define MATMUL(r0, r1, r2)                                                   \
    do {                                                                     \
        float n00 = fmaf(m00, (r0).x, fmaf(m01, (r1).x, m02 * (r2).x));      \
        float n01 = fmaf(m00, (r0).y, fmaf(m01, (r1).y, m02 * (r2).y));      \
        float n02 = fmaf(m00, (r0).z, fmaf(m01, (r1).z, m02 * (r2).z));      \
        float n10 = fmaf(m10, (r0).x, fmaf(m11, (r1).x, m12 * (r2).x));      \
        float n11 = fmaf(m10, (r0).y, fmaf(m11, (r1).y, m12 * (r2).y));      \
        float n12 = fmaf(m10, (r0).z, fmaf(m11, (r1).z, m12 * (r2).z));      \
        float n20 = fmaf(m20, (r0).x, fmaf(m21, (r1).x, m22 * (r2).x));      \
        float n21 = fmaf(m20, (r0).y, fmaf(m21, (r1).y, m22 * (r2).y));      \
        float n22 = fmaf(m20, (r0).z, fmaf(m21, (r1).z, m22 * (r2).z));      \
        m00 = n00; m01 = n01; m02 = n02;                                     \
        m10 = n10; m11 = n11; m12 = n12;                                     \
        m20 = n20; m21 = n21; m22 = n22;                                     \
    } while (0)

#define MAM()                                                       \
    do {                                                            \
        m00 *= scp; m01 *= scp; m02 *= scp;                         \
        m10 *= scp; m11 *= scp; m12 *= scp;                         \
        m20 *= scp; m21 *= scp; m22 *= scp;                         \
        etot += ep;                                                 \
        float s_ = m00 + m01 + m02;                                 \
        unsigned eb_ = __float_as_uint(s_) >> 23;                   \
        ep  = (int)eb_ - 127;                                       \
        scp = __uint_as_float((254u - eb_) << 23);                  \
    } while (0)

__global__ void __launch_bounds__(FBLK) forward_kernel(float* __restrict__ out) {
    __shared__ float4   t1[768];              // 12 KB table
    __shared__ unsigned sw[FROWS][WORDS + 1]; // +1 pad: stride 65 words -> no conflicts
    __shared__ float    cmb[FROWS][33];       // segs 1-3 results: 3 x (9 mat + etot)
    int tid = threadIdx.x;

    #pragma unroll
    for (int i = tid; i < 768; i += FBLK) t1[i] = g_tab1[i];
    const unsigned* src = g_packed + (size_t)blockIdx.x * FROWS * WORDS;
    #pragma unroll
    for (int i = tid; i < FROWS * WORDS; i += FBLK) sw[i >> 6][i & 63] = src[i];
    __syncthreads();

    int row = tid & 31;
    int seg = tid >> 5;                       // warp-uniform
    const unsigned* myw = &sw[row][seg << 4];

    float v0 = 0.f, v1 = 0.f, v2 = 0.f;       // seg0 result
    int   etot = 0, ep = 0;
    float scp = 1.0f;

    if (seg == 0) {
        v0 = g_pi[0]; v1 = g_pi[1]; v2 = g_pi[2];
        #pragma unroll 4
        for (int w = 0; w < 16; w++) {
            unsigned word = myw[w];
            unsigned b0 = word & 255u, b1 = (word >> 8) & 255u;
            unsigned b2 = (word >> 16) & 255u, b3 = word >> 24;
            mulvec(v0, v1, v2, t1[b0 * 3], t1[b0 * 3 + 1], t1[b0 * 3 + 2]);
            mulvec(v0, v1, v2, t1[b1 * 3], t1[b1 * 3 + 1], t1[b1 * 3 + 2]);
            VAM();
            mulvec(v0, v1, v2, t1[b2 * 3], t1[b2 * 3 + 1], t1[b2 * 3 + 2]);
            mulvec(v0, v1, v2, t1[b3 * 3], t1[b3 * 3 + 1], t1[b3 * 3 + 2]);
            VAM();
        }
        // pending (scp, ep) dropped together: exact identity on the tracked value
    } else {
        float m00 = 1.f, m01 = 0.f, m02 = 0.f;
        float m10 = 0.f, m11 = 1.f, m12 = 0.f;
        float m20 = 0.f, m21 = 0.f, m22 = 1.f;
        bool last_seg = (seg == 3);
        #pragma unroll 2
        for (int w = 0; w < 16; w++) {
            unsigned word = myw[w];
            unsigned b0 = word & 255u, b1 = (word >> 8) & 255u;
            unsigned b2 = (word >> 16) & 255u, b3 = word >> 24;
            MATMUL(t1[b0 * 3], t1[b0 * 3 + 1], t1[b0 * 3 + 2]);
            MATMUL(t1[b1 * 3], t1[b1 * 3 + 1], t1[b1 * 3 + 2]);
            MAM();
            MATMUL(t1[b2 * 3], t1[b2 * 3 + 1], t1[b2 * 3 + 2]);
            if (last_seg && w == 15) {
                // final byte of the row: 7 K's + trailing emission diag
                const float4* m2 = g_tab2 + b3 * 3;   // L2-served, once per row
                MATMUL(__ldg(m2), __ldg(m2 + 1), __ldg(m2 + 2));
            } else {
                MATMUL(t1[b3 * 3], t1[b3 * 3 + 1], t1[b3 * 3 + 2]);
            }
            MAM();
        }
        float* c = &cmb[row][(seg - 1) * 11];
        c[0] = m00; c[1] = m01; c[2] = m02;
        c[3] = m10; c[4] = m11; c[5] = m12;
        c[6] = m20; c[7] = m21; c[8] = m22;
        c[9] = __int_as_float(etot);
    }
    __syncthreads();

    if (seg == 0) {
        // combine: v <- v * M1 * M2 * M3 with exponent tracking
        #pragma unroll
        for (int s = 0; s < 3; s++) {
            const float* M = &cmb[row][s * 11];
            float n0 = fmaf(v0, M[0], fmaf(v1, M[3], v2 * M[6]));
            float n1 = fmaf(v0, M[1], fmaf(v1, M[4], v2 * M[7]));
            float n2 = fmaf(v0, M[2], fmaf(v1, M[5], v2 * M[8]));
            etot += __float_as_int(M[9]);
            float s_ = n0 + n1 + n2;
            unsigned eb = __float_as_uint(s_) >> 23;
            etot += (int)eb - 127;
            float sc = __uint_as_float((254u - eb) << 23);
            v0 = n0 * sc; v1 = n1 * sc; v2 = n2 * sc;
        }
        float logp = logf(v0 + v1 + v2) + (float)etot * 0.69314718055994530942f;

        // warp-level double reduce across the 32 rows of this block
        double d = (double)logp;
        #pragma unroll
        for (int off = 16; off > 0; off >>= 1)
            d += __shfl_down_sync(0xFFFFFFFFu, d, off);

        if (row == 0) {
            long long fx = __double2ll_rn(d * 4294967296.0);    // 2^32 fixed point
            atomicAdd(&g_acc, (unsigned long long)fx);          // exact, associative
            __threadfence();
            unsigned prev = atomicAdd(&g_done, 1u);
            if (prev == FGRID - 1) {
                unsigned long long a = atomicAdd(&g_acc, 0ull); // ordered read
                double tot = (double)(long long)a * (1.0 / 4294967296.0);
                out[0] = (float)(tot / (double)BATCH);
            }
        }
    }
}

// ---------------- launch: 2 graph nodes ----------------
extern "C" void kernel_launch(void* const* d_in, const int* in_sizes, int n_in,
                              void* d_out, int out_size) {
    const int*   y = (const int*)d_in[0];
    const float* T = (const float*)d_in[1];
    const float* E = (const float*)d_in[2];
    const float* S = (const float*)d_in[3];

    prep_kernel<<<2049, 256>>>(y, T, E, S);      // 2048 pack blocks + 1 fp32 precompute
    forward_kernel<<<FGRID, FBLK>>>((float*)d_out);
}